// round 17
// baseline (speedup 1.0000x reference)
#include <cuda_runtime.h>
#include <cuda_bf16.h>
#include <math.h>

// ---------------- static config ----------------
#define TOK_STRIDE 32768                 // 128 c * 256 hw
#define TOTAL (8*256*32768)

// ---------------- scratch (all bf16 feature buffers) ----------------
__device__ __nv_bfloat16 g_q[TOTAL];     // Q, later attention output o
__device__ __nv_bfloat16 g_k[TOTAL];     // K, later MLP hidden h
__device__ __nv_bfloat16 g_v[TOTAL];     // V
__device__ __nv_bfloat16 g_x[TOTAL];     // bf16(v), later bf16(mid)
__device__ float g_attn[8*16*4*256];
__device__ float g_mean[8*256*128];
__device__ float g_rsig[8*256*128];

// ---------------- helpers ----------------
__device__ __forceinline__ float gelu_tanh(float x) {
    float x3 = x * x * x;
    return 0.5f * x * (1.0f + tanhf(0.7978845608028654f * (x + 0.044715f * x3)));
}
__device__ __forceinline__ unsigned bfbits(__nv_bfloat162 h) { return *(unsigned*)&h; }
__device__ __forceinline__ int tok_of(int n, int slot) {
    int nr = n >> 2, nc = n & 3;
    int pr = nr * 4 + (slot >> 2), pc = nc * 4 + (slot & 3);
    return (((pr + 2) & 15) << 4) | ((pc + 2) & 15);
}
__device__ __forceinline__ int region_of(int p) { return p < 12 ? 0 : (p < 14 ? 1 : 2); }

// ---------------- convert v -> bf16 + InstanceNorm stats ----------------
__global__ __launch_bounds__(256) void conv_stats_kernel(const float* __restrict__ in,
                                                         __nv_bfloat16* __restrict__ outb,
                                                         float* __restrict__ mean,
                                                         float* __restrict__ rsig) {
    int row  = blockIdx.x * 8 + (threadIdx.x >> 5);
    int lane = threadIdx.x & 31;
    const float* p = in + (size_t)row * 256 + lane * 8;
    float4 a = *(const float4*)p;
    float4 b = *(const float4*)(p + 4);
    float s = a.x + a.y + a.z + a.w + b.x + b.y + b.z + b.w;
    float q = a.x*a.x + a.y*a.y + a.z*a.z + a.w*a.w
            + b.x*b.x + b.y*b.y + b.z*b.z + b.w*b.w;
#pragma unroll
    for (int off = 16; off; off >>= 1) {
        s += __shfl_xor_sync(0xffffffffu, s, off);
        q += __shfl_xor_sync(0xffffffffu, q, off);
    }
    uint4 o;
    o.x = bfbits(__floats2bfloat162_rn(a.x, a.y));
    o.y = bfbits(__floats2bfloat162_rn(a.z, a.w));
    o.z = bfbits(__floats2bfloat162_rn(b.x, b.y));
    o.w = bfbits(__floats2bfloat162_rn(b.z, b.w));
    *(uint4*)&outb[(size_t)row * 256 + lane * 8] = o;
    if (lane == 0) {
        float m = s * (1.0f / 256.0f);
        float var = q * (1.0f / 256.0f) - m * m;
        mean[row] = m;
        rsig[row] = rsqrtf(var + 1e-5f);
    }
}

// ---------------- InstanceNorm stats only (fp32 input) ----------------
__global__ __launch_bounds__(256) void stats_kernel(const float* __restrict__ in,
                                                    float* __restrict__ mean,
                                                    float* __restrict__ rsig) {
    int row  = blockIdx.x * 8 + (threadIdx.x >> 5);
    int lane = threadIdx.x & 31;
    const float* p = in + (size_t)row * 256 + lane * 8;
    float4 a = *(const float4*)p;
    float4 b = *(const float4*)(p + 4);
    float s = a.x + a.y + a.z + a.w + b.x + b.y + b.z + b.w;
    float q = a.x*a.x + a.y*a.y + a.z*a.z + a.w*a.w
            + b.x*b.x + b.y*b.y + b.z*b.z + b.w*b.w;
#pragma unroll
    for (int off = 16; off; off >>= 1) {
        s += __shfl_xor_sync(0xffffffffu, s, off);
        q += __shfl_xor_sync(0xffffffffu, q, off);
    }
    if (lane == 0) {
        float m = s * (1.0f / 256.0f);
        float var = q * (1.0f / 256.0f) - m * m;
        mean[row] = m;
        rsig[row] = rsqrtf(var + 1e-5f);
    }
}

// ---------------- bf16 tensor-core pointwise GEMM (cp.async + ldmatrix) ----------------
// Out[d=128][hw slice 128] = sum_c W'[c][d] * Xbf[c][hw] (+ bias - corr)
// Block = (mat*2+nhalf, bs), 128 thr = 4 warps (2m x 2n), warp tile 64x64.
// X: bf16 gmem, cp.async double-buffered. W: fp32 gmem -> scaled bf16 smem.
// Norm folding: W' = W * rsig_k;  bias_corr[m] = sum_k W'[k][m]*mean_k.
// mode: 0 plain, 1 gelu, 2 +residual
__global__ __launch_bounds__(128) void pw_tc_kernel(
    const __nv_bfloat16* __restrict__ Xg,
    const float* __restrict__ W0, const float* __restrict__ W1, const float* __restrict__ W2,
    const float* __restrict__ B0, const float* __restrict__ B1, const float* __restrict__ B2,
    __nv_bfloat16* __restrict__ Ob0, __nv_bfloat16* __restrict__ Ob1, __nv_bfloat16* __restrict__ Ob2,
    float* __restrict__ Of,
    __nv_bfloat16* __restrict__ Shadow,
    const float* __restrict__ mean, const float* __restrict__ rsig,
    const float* __restrict__ res, int mode)
{
    __shared__ __align__(16) __nv_bfloat16 Xs[2][16][136];
    __shared__ __align__(16) __nv_bfloat16 Wsm[2][16][136];
    __shared__ float corr[128];

    const int bs  = blockIdx.y;
    const int mat = blockIdx.x >> 1;
    const int n0  = (blockIdx.x & 1) * 128;
    const float* W  = (mat == 0) ? W0 : (mat == 1 ? W1 : W2);
    const float* Bp = (mat == 0) ? B0 : (mat == 1 ? B1 : B2);
    __nv_bfloat16* Ob = (mat == 0) ? Ob0 : (mat == 1 ? Ob1 : Ob2);
    const __nv_bfloat16* Xb = Xg + (size_t)bs * TOK_STRIDE + n0;

    const int tid = threadIdx.x;
    const int warp = tid >> 5, lane = tid & 31;
    const int gid = lane >> 2, tig = lane & 3;
    const int m_warp = (warp >> 1) * 64;
    const int n_warp = (warp & 1) * 64;
    const bool norm = (mean != nullptr);

    if (norm && tid < 128) corr[tid] = 0.f;
    __syncthreads();

    float acc[4][8][4];
#pragma unroll
    for (int a = 0; a < 4; a++)
#pragma unroll
        for (int b = 0; b < 8; b++)
#pragma unroll
            for (int c = 0; c < 4; c++) acc[a][b][c] = 0.0f;

    const int wrow = tid >> 3;            // 0..15 (k within chunk)
    const int wm   = (tid & 7) * 16;      // 16 m per thread
    float4 wreg[4];
    float partial[16];
    if (norm) {
#pragma unroll
        for (int j = 0; j < 16; j++) partial[j] = 0.f;
    }

#define ISSUE_X(T, NB) do {                                                        \
    int k0_ = (T) * 16;                                                            \
    _Pragma("unroll")                                                              \
    for (int i = 0; i < 2; i++) {                                                  \
        int seg = tid + i * 128;                                                   \
        int row = seg >> 4, c8 = (seg & 15) * 8;                                   \
        unsigned dst = (unsigned)__cvta_generic_to_shared(&Xs[NB][row][c8]);       \
        const __nv_bfloat16* src = Xb + (size_t)(k0_ + row) * 256 + c8;            \
        asm volatile("cp.async.cg.shared.global [%0], [%1], 16;\n"                 \
                     :: "r"(dst), "l"(src));                                       \
    }                                                                              \
    asm volatile("cp.async.commit_group;\n");                                      \
} while (0)

#define LD_W(T) do {                                                               \
    const float* wp_ = W + ((T) * 16 + wrow) * 128 + wm;                           \
    _Pragma("unroll")                                                              \
    for (int g = 0; g < 4; g++) wreg[g] = *(const float4*)(wp_ + g * 4);           \
} while (0)

#define ST_W(T, NB) do {                                                           \
    float rk_ = 1.f, mk_ = 0.f;                                                    \
    if (norm) {                                                                    \
        int c_ = (T) * 16 + wrow;                                                  \
        rk_ = __ldg(&rsig[bs * 128 + c_]);                                         \
        mk_ = __ldg(&mean[bs * 128 + c_]);                                         \
    }                                                                              \
    unsigned hw_[8];                                                               \
    _Pragma("unroll")                                                              \
    for (int g = 0; g < 4; g++) {                                                  \
        float x0 = wreg[g].x, x1 = wreg[g].y, x2 = wreg[g].z, x3 = wreg[g].w;      \
        if (norm) { x0 *= rk_; x1 *= rk_; x2 *= rk_; x3 *= rk_; }                  \
        __nv_bfloat162 h0 = __floats2bfloat162_rn(x0, x1);                         \
        __nv_bfloat162 h1 = __floats2bfloat162_rn(x2, x3);                         \
        hw_[2*g] = bfbits(h0); hw_[2*g+1] = bfbits(h1);                            \
        if (norm) {                                                                \
            partial[4*g+0] += __low2float(h0)  * mk_;                              \
            partial[4*g+1] += __high2float(h0) * mk_;                              \
            partial[4*g+2] += __low2float(h1)  * mk_;                              \
            partial[4*g+3] += __high2float(h1) * mk_;                              \
        }                                                                          \
    }                                                                              \
    *(uint4*)&Wsm[NB][wrow][wm]     = make_uint4(hw_[0], hw_[1], hw_[2], hw_[3]);  \
    *(uint4*)&Wsm[NB][wrow][wm + 8] = make_uint4(hw_[4], hw_[5], hw_[6], hw_[7]);  \
} while (0)

    ISSUE_X(0, 0);
    LD_W(0);

#pragma unroll 1
    for (int t = 0; t < 8; t++) {
        const int buf = t & 1;
        if (t < 7) ISSUE_X(t + 1, buf ^ 1);
        ST_W(t, buf);
        if (t < 7) LD_W(t + 1);
        if (t < 7) asm volatile("cp.async.wait_group 1;\n" ::);
        else       asm volatile("cp.async.wait_group 0;\n" ::);
        __syncthreads();

        // A fragments via ldmatrix.x4.trans from Wsm [k][m]
        unsigned af[4][4];
        {
            int krow = ((lane >> 4) & 1) * 8 + (lane & 7);
            int mcol = ((lane >> 3) & 1) * 8;
#pragma unroll
            for (int mt = 0; mt < 4; mt++) {
                unsigned aaddr = (unsigned)__cvta_generic_to_shared(
                    &Wsm[buf][krow][m_warp + mt * 16 + mcol]);
                asm volatile(
                    "ldmatrix.sync.aligned.m8n8.x4.trans.shared.b16 {%0,%1,%2,%3},[%4];"
                    : "=r"(af[mt][0]), "=r"(af[mt][1]), "=r"(af[mt][2]), "=r"(af[mt][3])
                    : "r"(aaddr));
            }
        }
        // B fragments + MMA
        {
            int krow = ((lane >> 3) & 1) * 8 + (lane & 7);
            int noff = (lane >> 4) * 8;
#pragma unroll
            for (int ng = 0; ng < 4; ng++) {
                unsigned bb[4];
                unsigned baddr = (unsigned)__cvta_generic_to_shared(
                    &Xs[buf][krow][n_warp + ng * 16 + noff]);
                asm volatile(
                    "ldmatrix.sync.aligned.m8n8.x4.trans.shared.b16 {%0,%1,%2,%3},[%4];"
                    : "=r"(bb[0]), "=r"(bb[1]), "=r"(bb[2]), "=r"(bb[3])
                    : "r"(baddr));
#pragma unroll
                for (int s = 0; s < 2; s++) {
                    const int nt = ng * 2 + s;
#pragma unroll
                    for (int mt = 0; mt < 4; mt++) {
                        float* c = acc[mt][nt];
                        asm volatile(
                            "mma.sync.aligned.m16n8k16.row.col.f32.bf16.bf16.f32 "
                            "{%0,%1,%2,%3},{%4,%5,%6,%7},{%8,%9},{%0,%1,%2,%3};"
                            : "+f"(c[0]), "+f"(c[1]), "+f"(c[2]), "+f"(c[3])
                            : "r"(af[mt][0]), "r"(af[mt][1]), "r"(af[mt][2]), "r"(af[mt][3]),
                              "r"(bb[2*s]), "r"(bb[2*s+1]));
                    }
                }
            }
        }
        __syncthreads();
    }
#undef ISSUE_X
#undef LD_W
#undef ST_W

    if (norm) {
#pragma unroll
        for (int j = 0; j < 16; j++) atomicAdd(&corr[wm + j], partial[j]);
        __syncthreads();
    }

    // ---------- epilogue ----------
    const float* Rb = res ? res + (size_t)bs * TOK_STRIDE + n0 : nullptr;
    float* Ofb = Of ? Of + (size_t)bs * TOK_STRIDE + n0 : nullptr;
    __nv_bfloat16* Shb = Shadow ? Shadow + (size_t)bs * TOK_STRIDE + n0 : nullptr;
    __nv_bfloat16* Obb = Ob ? Ob + (size_t)bs * TOK_STRIDE + n0 : nullptr;

#pragma unroll
    for (int mt = 0; mt < 4; mt++) {
        int m0 = m_warp + mt * 16 + gid;
        float bv0 = __ldg(&Bp[m0])     - (norm ? corr[m0]     : 0.f);
        float bv1 = __ldg(&Bp[m0 + 8]) - (norm ? corr[m0 + 8] : 0.f);
#pragma unroll
        for (int nt = 0; nt < 8; nt++) {
            int col = n_warp + nt * 8 + 2 * tig;
            float o00 = acc[mt][nt][0] + bv0, o01 = acc[mt][nt][1] + bv0;
            float o10 = acc[mt][nt][2] + bv1, o11 = acc[mt][nt][3] + bv1;
            if (mode == 1) {
                o00 = gelu_tanh(o00); o01 = gelu_tanh(o01);
                o10 = gelu_tanh(o10); o11 = gelu_tanh(o11);
            } else if (mode == 2) {
                float2 r0 = *(const float2*)&Rb[m0 * 256 + col];
                float2 r1 = *(const float2*)&Rb[(m0 + 8) * 256 + col];
                o00 += r0.x; o01 += r0.y; o10 += r1.x; o11 += r1.y;
            }
            if (Ofb) {
                *(float2*)&Ofb[m0 * 256 + col]       = make_float2(o00, o01);
                *(float2*)&Ofb[(m0 + 8) * 256 + col] = make_float2(o10, o11);
                if (Shb) {
                    *(unsigned*)&Shb[m0 * 256 + col]       = bfbits(__floats2bfloat162_rn(o00, o01));
                    *(unsigned*)&Shb[(m0 + 8) * 256 + col] = bfbits(__floats2bfloat162_rn(o10, o11));
                }
            } else {
                *(unsigned*)&Obb[m0 * 256 + col]       = bfbits(__floats2bfloat162_rn(o00, o01));
                *(unsigned*)&Obb[(m0 + 8) * 256 + col] = bfbits(__floats2bfloat162_rn(o10, o11));
            }
        }
    }
}

// ---------------- scores + mask + softmax (bf16 Q,K) ----------------
__global__ __launch_bounds__(256) void scores_kernel(const __nv_bfloat16* __restrict__ qb,
                                                     const __nv_bfloat16* __restrict__ kb,
                                                     float* __restrict__ attn) {
    __shared__ float qs[16][260];
    __shared__ float ks[16][260];
    __shared__ int toks[16];
    const int blk = blockIdx.x;
    const int h = blk & 3;
    const int bn = blk >> 2;
    const int n = bn & 15;
    const int b = bn >> 4;
    const int tid = threadIdx.x;
    if (tid < 16) toks[tid] = tok_of(n, tid);
    __syncthreads();

    const int t = tid >> 4, s = tid & 15;
    float ax = 0.f, ay = 0.f, az = 0.f, aw = 0.f;

    for (int ch = 0; ch < 32; ch++) {
        __syncthreads();
#pragma unroll
        for (int j = 0; j < 4; j++) {
            int p = tid + j * 256;
            int row = p >> 5;
            int c8 = (p & 31) << 3;
            const __nv_bfloat16* src = (row < 16) ? qb : kb;
            int tok = toks[row & 15];
            const __nv_bfloat16* g = src + ((size_t)(b * 256 + tok)) * TOK_STRIDE
                                         + h * 8192 + ch * 256 + c8;
            uint4 u = *(const uint4*)g;
            float2 f0 = __bfloat1622float2(*(__nv_bfloat162*)&u.x);
            float2 f1 = __bfloat1622float2(*(__nv_bfloat162*)&u.y);
            float2 f2 = __bfloat1622float2(*(__nv_bfloat162*)&u.z);
            float2 f3 = __bfloat1622float2(*(__nv_bfloat162*)&u.w);
            float* dst = (row < 16 ? qs : ks)[row & 15] + c8;
            *(float4*)dst       = make_float4(f0.x, f0.y, f1.x, f1.y);
            *(float4*)(dst + 4) = make_float4(f2.x, f2.y, f3.x, f3.y);
        }
        __syncthreads();
#pragma unroll
        for (int i4 = 0; i4 < 64; i4++) {
            float4 qv = *(float4*)&qs[t][i4 * 4];
            float4 kv = *(float4*)&ks[s][i4 * 4];
            ax += qv.x * kv.x; ay += qv.y * kv.y;
            az += qv.z * kv.z; aw += qv.w * kv.w;
        }
    }
    float acc = (ax + ay) + (az + aw);
    acc *= 6.9053396600248786e-4f;

    {
        int nr = n >> 2, nc = n & 3;
        int idt = region_of(nr * 4 + (t >> 2)) * 3 + region_of(nc * 4 + (t & 3));
        int ids = region_of(nr * 4 + (s >> 2)) * 3 + region_of(nc * 4 + (s & 3));
        if (idt != ids) acc -= 1e9f;
    }

    float m = acc;
#pragma unroll
    for (int off = 8; off; off >>= 1)
        m = fmaxf(m, __shfl_xor_sync(0xffffffffu, m, off, 16));
    float e = expf(acc - m);
    float sum = e;
#pragma unroll
    for (int off = 8; off; off >>= 1)
        sum += __shfl_xor_sync(0xffffffffu, sum, off, 16);

    attn[blk * 256 + tid] = e / sum;
}

// ---------------- attn @ V (bf16 V in, bf16 o out) ----------------
__global__ __launch_bounds__(256, 2) void apply_attn_kernel(const float* __restrict__ attn,
                                                            const __nv_bfloat16* __restrict__ val,
                                                            __nv_bfloat16* __restrict__ out) {
    __shared__ float at_s[16][16];
    __shared__ int toks[16];
    const int bn = blockIdx.y;
    const int b = bn >> 4, n = bn & 15;
    const int tid = threadIdx.x;
    if (tid < 16) toks[tid] = tok_of(n, tid);

    const int f0 = blockIdx.x * 1024 + tid * 4;
    const int c = f0 >> 8;
    const int hw = f0 & 255;
    const int head = c >> 5;
    at_s[tid >> 4][tid & 15] = attn[(bn * 4 + head) * 256 + tid];
    __syncthreads();

    float4 vf[16];
#pragma unroll
    for (int s = 0; s < 16; s++) {
        uint2 raw = *(const uint2*)&val[((size_t)(b * 256 + toks[s])) * TOK_STRIDE + c * 256 + hw];
        float2 lo = __bfloat1622float2(*(__nv_bfloat162*)&raw.x);
        float2 hi = __bfloat1622float2(*(__nv_bfloat162*)&raw.y);
        vf[s] = make_float4(lo.x, lo.y, hi.x, hi.y);
    }

#pragma unroll
    for (int t = 0; t < 16; t++) {
        float4 o = make_float4(0.f, 0.f, 0.f, 0.f);
#pragma unroll
        for (int s = 0; s < 16; s++) {
            float a = at_s[t][s];
            o.x += a * vf[s].x; o.y += a * vf[s].y;
            o.z += a * vf[s].z; o.w += a * vf[s].w;
        }
        uint2 packed;
        packed.x = bfbits(__floats2bfloat162_rn(o.x, o.y));
        packed.y = bfbits(__floats2bfloat162_rn(o.z, o.w));
        *(uint2*)&out[((size_t)(b * 256 + toks[t])) * TOK_STRIDE + c * 256 + hw] = packed;
    }
}

// ---------------- launch ----------------
extern "C" void kernel_launch(void* const* d_in, const int* in_sizes, int n_in,
                              void* d_out, int out_size) {
    const float* v  = (const float*)d_in[0];
    const float* wq = (const float*)d_in[1];
    const float* bq = (const float*)d_in[2];
    const float* wk = (const float*)d_in[3];
    const float* bk = (const float*)d_in[4];
    const float* wv = (const float*)d_in[5];
    const float* bv = (const float*)d_in[6];
    const float* wo = (const float*)d_in[7];
    const float* bo = (const float*)d_in[8];
    const float* w1 = (const float*)d_in[9];
    const float* b1 = (const float*)d_in[10];
    const float* w2 = (const float*)d_in[11];
    const float* b2 = (const float*)d_in[12];
    float* out = (float*)d_out;

    __nv_bfloat16 *qb, *kb, *vb, *xb;
    float *attn, *mean, *rsig;
    cudaGetSymbolAddress((void**)&qb,   g_q);
    cudaGetSymbolAddress((void**)&kb,   g_k);
    cudaGetSymbolAddress((void**)&vb,   g_v);
    cudaGetSymbolAddress((void**)&xb,   g_x);
    cudaGetSymbolAddress((void**)&attn, g_attn);
    cudaGetSymbolAddress((void**)&mean, g_mean);
    cudaGetSymbolAddress((void**)&rsig, g_rsig);

    // 1. bf16(v) + InstanceNorm stats in one pass
    conv_stats_kernel<<<32768, 256>>>(v, xb, mean, rsig);
    // 2. Q,K,V projections (norm folded into W), bf16 outputs
    pw_tc_kernel<<<dim3(6, 2048), 128>>>(xb, wq, wk, wv, bq, bk, bv,
                                         qb, kb, vb, nullptr, nullptr,
                                         mean, rsig, nullptr, 0);
    // 3. scores + mask + softmax
    scores_kernel<<<512, 256>>>(qb, kb, attn);
    // 4. o = attn @ V (bf16 -> bf16, overwrites Q)
    apply_attn_kernel<<<dim3(32, 128), 256>>>(attn, vb, qb);
    // 5. mid = v + pw(o, w_o): fp32 out + bf16 shadow (reuses g_x)
    pw_tc_kernel<<<dim3(2, 2048), 128>>>(qb, wo, wo, wo, bo, bo, bo,
                                         nullptr, nullptr, nullptr, out, xb,
                                         nullptr, nullptr, v, 2);
    // 6. InstanceNorm stats of mid
    stats_kernel<<<32768, 256>>>(out, mean, rsig);
    // 7. h = gelu(pw(norm(mid), w1)), bf16 out (overwrites K)
    pw_tc_kernel<<<dim3(2, 2048), 128>>>(xb, w1, w1, w1, b1, b1, b1,
                                         kb, kb, kb, nullptr, nullptr,
                                         mean, rsig, nullptr, 1);
    // 8. out = mid + pw(h, w2), fp32
    pw_tc_kernel<<<dim3(2, 2048), 128>>>(kb, w2, w2, w2, b2, b2, b2,
                                         nullptr, nullptr, nullptr, out, nullptr,
                                         nullptr, nullptr, out, 2);
}